// round 3
// baseline (speedup 1.0000x reference)
#include <cuda_runtime.h>
#include <math.h>
#include <float.h>

// ---------------- problem constants ----------------
#define BB    128
#define NN    197
#define CC    768
#define NHEAD 12
#define HD    64
#define H3    2304          // 3*C
#define HID   3072          // 4*C
#define NT    (BB*NN)       // 25216 tokens
#define NM1   (NN-1)        // 196
#define LEFT  138           // ceil(0.7*196)
#define NCMP  58            // 196-138
#define N2    (LEFT+1)      // 139
#define NT2   (BB*N2)       // 17792 tokens

// ---------------- scratch (device globals; no allocations allowed) ----------------
__device__ float  g_xn  [(size_t)NT*CC];       // layernorm1 out (fp32 path)
__device__ float  g_qkv [(size_t)NT*H3];       // qkv
__device__ float  g_ao  [(size_t)NT*CC];       // attention out
__device__ float  g_x1  [(size_t)NT*CC];       // x + proj(out)
__device__ double g_mu  [(size_t)NT];          // fp64 LN1 mean per token
__device__ double g_rs  [(size_t)NT];          // fp64 LN1 rstd per token
__device__ double g_at0d[(size_t)BB*NHEAD*NM1];// fp64 cls row probs (truth)
__device__ float  g_cls [(size_t)BB*NM1];      // mean over heads (fp32, for weights)
__device__ double g_clsd[(size_t)BB*NM1];      // mean over heads (fp64, for selection)
__device__ int    g_idx [(size_t)BB*LEFT];
__device__ int    g_cmp [(size_t)BB*NCMP];
__device__ float  g_xon [(size_t)BB*LEFT*CC];  // normalized topk rows
__device__ float  g_ntn [(size_t)BB*NCMP*CC];  // normalized non-topk rows
__device__ int    g_nod [(size_t)BB*NCMP];     // argmax targets
__device__ float  g_x2  [(size_t)NT2*CC];      // fused tokens
__device__ float  g_xn2 [(size_t)NT2*CC];      // layernorm2 out
__device__ float  g_mid [(size_t)NT2*HID];     // gelu(fc1)

// ---------------- helpers ----------------
__device__ __forceinline__ float blockReduceSum(float v, float* sh) {
    int tid = threadIdx.x;
    #pragma unroll
    for (int o = 16; o > 0; o >>= 1) v += __shfl_down_sync(0xffffffffu, v, o);
    __syncthreads();
    if ((tid & 31) == 0) sh[tid >> 5] = v;
    __syncthreads();
    int nw = blockDim.x >> 5;
    float r = (tid < nw) ? sh[tid] : 0.f;
    if (tid < 32) {
        #pragma unroll
        for (int o = 16; o > 0; o >>= 1) r += __shfl_down_sync(0xffffffffu, r, o);
        if (tid == 0) sh[0] = r;
    }
    __syncthreads();
    return sh[0];
}

__device__ __forceinline__ double blockReduceSumD(double v, double* sh) {
    int tid = threadIdx.x;
    #pragma unroll
    for (int o = 16; o > 0; o >>= 1) v += __shfl_down_sync(0xffffffffu, v, o);
    __syncthreads();
    if ((tid & 31) == 0) sh[tid >> 5] = v;
    __syncthreads();
    int nw = blockDim.x >> 5;
    double r = (tid < nw) ? sh[tid] : 0.0;
    if (tid < 32) {
        #pragma unroll
        for (int o = 16; o > 0; o >>= 1) r += __shfl_down_sync(0xffffffffu, r, o);
        if (tid == 0) sh[0] = r;
    }
    __syncthreads();
    return sh[0];
}

// ---------------- layernorm (fp32 path) ----------------
__global__ void ln_kernel(const float* __restrict__ x, const float* __restrict__ w,
                          const float* __restrict__ b, float* __restrict__ y) {
    __shared__ float sh[32];
    const size_t t = blockIdx.x;
    const float* row = x + t * CC;
    float* out = y + t * CC;
    float s = 0.f;
    for (int c = threadIdx.x; c < CC; c += blockDim.x) s += row[c];
    float mean = blockReduceSum(s, sh) * (1.f / CC);
    float v = 0.f;
    for (int c = threadIdx.x; c < CC; c += blockDim.x) { float d = row[c] - mean; v += d * d; }
    float var = blockReduceSum(v, sh) * (1.f / CC);
    float rstd = rsqrtf(var + 1e-5f);
    for (int c = threadIdx.x; c < CC; c += blockDim.x)
        out[c] = (row[c] - mean) * rstd * w[c] + b[c];
}

// ---------------- fp64 LN stats per token (truth path) ----------------
__global__ void ln64stats_kernel(const float* __restrict__ x, double* __restrict__ mu,
                                 double* __restrict__ rs) {
    __shared__ double sh[32];
    const size_t t = blockIdx.x;
    const float* row = x + t * CC;
    double s = 0.0;
    for (int c = threadIdx.x; c < CC; c += blockDim.x) s += (double)row[c];
    double mean = blockReduceSumD(s, sh) * (1.0 / CC);
    double v = 0.0;
    for (int c = threadIdx.x; c < CC; c += blockDim.x) { double d = (double)row[c] - mean; v += d * d; }
    double var = blockReduceSumD(v, sh) * (1.0 / CC);
    if (threadIdx.x == 0) { mu[t] = mean; rs[t] = rsqrt(var + 1e-5); }
}

// ---------------- truth cls scores: grid (h, b), 256 threads ----------------
// s_j^(h) = (W_q^(h)T xn0) . (W_k^(h)T xn_j) = u^(h) . xn_j  (all fp64)
__global__ void cls_truth_kernel(const float* __restrict__ x, const float* __restrict__ qw,
                                 const float* __restrict__ n1w, const float* __restrict__ n1b,
                                 const double* __restrict__ mu, const double* __restrict__ rs,
                                 double* __restrict__ at0d) {
    const int h = blockIdx.x, b = blockIdx.y, tid = threadIdx.x; // 256 threads
    __shared__ double xn0[CC];
    __shared__ double q0[HD];
    __shared__ double u[CC];
    __shared__ double sc[NN];
    __shared__ double sh[32];
    const double mu0 = mu[(size_t)b * NN], rs0 = rs[(size_t)b * NN];
    const float* x0 = x + ((size_t)b * NN) * CC;
    for (int c = tid; c < CC; c += blockDim.x)
        xn0[c] = ((double)x0[c] - mu0) * rs0 * (double)n1w[c] + (double)n1b[c];
    __syncthreads();
    // q0[d] = sum_c xn0[c] * qw[c, h*64+d]
    if (tid < HD) {
        double a0 = 0.0, a1 = 0.0;
        const float* col = qw + h * HD + tid;
        for (int c = 0; c < CC; c += 2) {
            a0 += xn0[c]     * (double)col[(size_t)c * H3];
            a1 += xn0[c + 1] * (double)col[(size_t)(c + 1) * H3];
        }
        q0[tid] = a0 + a1;
    }
    __syncthreads();
    // u[c] = sum_d qw[c, 768 + h*64+d] * q0[d]
    for (int c = tid; c < CC; c += blockDim.x) {
        const float* rowp = qw + (size_t)c * H3 + CC + h * HD;
        double a0 = 0.0, a1 = 0.0;
        #pragma unroll
        for (int d = 0; d < HD; d += 2) { a0 += (double)rowp[d] * q0[d]; a1 += (double)rowp[d + 1] * q0[d + 1]; }
        u[c] = a0 + a1;
    }
    __syncthreads();
    // s_j = 0.125 * sum_c u[c] * xn_j[c]
    for (int j = tid; j < NN; j += blockDim.x) {
        const float* xj = x + ((size_t)(b * NN + j)) * CC;
        const double mj = mu[(size_t)b * NN + j], rj = rs[(size_t)b * NN + j];
        double a0 = 0.0, a1 = 0.0;
        for (int c = 0; c < CC; c += 2) {
            a0 += u[c]     * (((double)xj[c]     - mj) * rj * (double)n1w[c]     + (double)n1b[c]);
            a1 += u[c + 1] * (((double)xj[c + 1] - mj) * rj * (double)n1w[c + 1] + (double)n1b[c + 1]);
        }
        sc[j] = (a0 + a1) * 0.125;
    }
    __syncthreads();
    // fp64 softmax over j = 0..196
    double m = -1e300;
    for (int j = tid; j < NN; j += blockDim.x) m = fmax(m, sc[j]);
    #pragma unroll
    for (int o = 16; o > 0; o >>= 1) m = fmax(m, __shfl_down_sync(0xffffffffu, m, o));
    __syncthreads();
    if ((tid & 31) == 0) sh[tid >> 5] = m;
    __syncthreads();
    if (tid < 32) {
        double r = (tid < (int)(blockDim.x >> 5)) ? sh[tid] : -1e300;
        #pragma unroll
        for (int o = 16; o > 0; o >>= 1) r = fmax(r, __shfl_down_sync(0xffffffffu, r, o));
        if (tid == 0) sh[0] = r;
    }
    __syncthreads();
    m = sh[0];
    __syncthreads();
    double ssum = 0.0;
    for (int j = tid; j < NN; j += blockDim.x) { double e = exp(sc[j] - m); sc[j] = e; ssum += e; }
    double tot = blockReduceSumD(ssum, sh);
    double inv = 1.0 / tot;
    __syncthreads();
    for (int j = tid; j < NM1; j += blockDim.x)
        at0d[((size_t)b * NHEAD + h) * NM1 + j] = sc[j + 1] * inv;
}

// ---------------- cls attention mean over heads (fp64 -> fp64 + fp32) ----------------
__global__ void clsmean_kernel(const double* __restrict__ at0d, float* __restrict__ cls,
                               double* __restrict__ clsd) {
    int i = blockIdx.x * blockDim.x + threadIdx.x;
    if (i >= BB * NM1) return;
    int b = i / NM1, j = i % NM1;
    double s = 0.0;
    #pragma unroll
    for (int h = 0; h < NHEAD; h++) s += at0d[((size_t)b * NHEAD + h) * NM1 + j];
    double mval = s * (1.0 / NHEAD);
    clsd[i] = mval;
    cls[i] = (float)mval;
}

// ---------------- SGEMM: C = A(MxK) @ B(KxN) (+epilogues) ----------------
__global__ void sgemm(const float* __restrict__ A, const float* __restrict__ Bw,
                      const float* __restrict__ bias, const float* __restrict__ Rm,
                      float* __restrict__ Cm, int M, int Nn, int K, int epi) {
    __shared__ float As[16][64];
    __shared__ float Bs[16][64];
    const int tid = threadIdx.x;
    const int tx = tid & 15, ty = tid >> 4;
    const int row0 = blockIdx.y * 64, col0 = blockIdx.x * 64;
    float acc[4][4] = {};
    for (int k0 = 0; k0 < K; k0 += 16) {
        #pragma unroll
        for (int i = 0; i < 4; i++) {
            int lin = tid + i * 256;
            int m = lin >> 4, kk = lin & 15;
            int gr = row0 + m;
            As[kk][m] = (gr < M) ? A[(size_t)gr * K + k0 + kk] : 0.f;
        }
        #pragma unroll
        for (int i = 0; i < 4; i++) {
            int kk = (tid >> 6) + i * 4;
            int n = tid & 63;
            Bs[kk][n] = Bw[(size_t)(k0 + kk) * Nn + col0 + n];
        }
        __syncthreads();
        #pragma unroll
        for (int kk = 0; kk < 16; kk++) {
            float a[4], bv[4];
            #pragma unroll
            for (int i = 0; i < 4; i++) a[i] = As[kk][ty * 4 + i];
            #pragma unroll
            for (int j = 0; j < 4; j++) bv[j] = Bs[kk][tx * 4 + j];
            #pragma unroll
            for (int i = 0; i < 4; i++)
                #pragma unroll
                for (int j = 0; j < 4; j++) acc[i][j] += a[i] * bv[j];
        }
        __syncthreads();
    }
    #pragma unroll
    for (int i = 0; i < 4; i++) {
        int r = row0 + ty * 4 + i;
        if (r >= M) continue;
        #pragma unroll
        for (int j = 0; j < 4; j++) {
            int c = col0 + tx * 4 + j;
            float v = acc[i][j];
            if (epi != 0) v += bias[c];
            if (epi == 1) v += Rm[(size_t)r * Nn + c];
            else if (epi == 2) v = 0.5f * v * (1.f + erff(v * 0.70710678118654752440f));
            Cm[(size_t)r * Nn + c] = v;
        }
    }
}

// ---------------- attention (fp32, output path) ----------------
__global__ void attn_kernel(const float* __restrict__ qkv, float* __restrict__ out) {
    const int q = blockIdx.x, h = blockIdx.y, b = blockIdx.z;
    const int tid = threadIdx.x;               // 128 threads
    __shared__ float qv[HD];
    __shared__ float sc[NN];
    __shared__ float sh[32];
    const float* qptr = qkv + ((size_t)(b * NN + q)) * H3 + h * HD;
    const float* kbase = qkv + ((size_t)b * NN) * H3 + (NHEAD + h) * HD;
    const float* vbase = qkv + ((size_t)b * NN) * H3 + (2 * NHEAD + h) * HD;
    if (tid < HD) qv[tid] = qptr[tid];
    __syncthreads();
    for (int k = tid; k < NN; k += blockDim.x) {
        const float* kp = kbase + (size_t)k * H3;
        float s = 0.f;
        #pragma unroll
        for (int d = 0; d < HD; d++) s += qv[d] * kp[d];
        sc[k] = s * 0.125f;
    }
    __syncthreads();
    float m = -FLT_MAX;
    for (int k = tid; k < NN; k += blockDim.x) m = fmaxf(m, sc[k]);
    #pragma unroll
    for (int o = 16; o > 0; o >>= 1) m = fmaxf(m, __shfl_down_sync(0xffffffffu, m, o));
    __syncthreads();
    if ((tid & 31) == 0) sh[tid >> 5] = m;
    __syncthreads();
    if (tid < 32) {
        float r = (tid < (int)(blockDim.x >> 5)) ? sh[tid] : -FLT_MAX;
        #pragma unroll
        for (int o = 16; o > 0; o >>= 1) r = fmaxf(r, __shfl_down_sync(0xffffffffu, r, o));
        if (tid == 0) sh[0] = r;
    }
    __syncthreads();
    m = sh[0];
    __syncthreads();
    float ssum = 0.f;
    for (int k = tid; k < NN; k += blockDim.x) { float e = expf(sc[k] - m); sc[k] = e; ssum += e; }
    float tot = blockReduceSum(ssum, sh);
    float inv = 1.f / tot;
    for (int k = tid; k < NN; k += blockDim.x) sc[k] *= inv;
    __syncthreads();
    if (tid < HD) {
        float acc = 0.f;
        for (int k = 0; k < NN; k++) acc += sc[k] * vbase[(size_t)k * H3 + tid];
        out[((size_t)(b * NN + q)) * CC + h * HD + tid] = acc;
    }
}

// ---------------- exact stable descending full sort via rank counting ----------------
__global__ void topk_kernel(const double* __restrict__ clsd, int* __restrict__ idx,
                            int* __restrict__ cmp) {
    const int b = blockIdx.x, tid = threadIdx.x;   // 256 threads
    __shared__ double v[NM1];
    __shared__ int order[NM1];
    __shared__ unsigned char taken[NM1];
    if (tid < NM1) { v[tid] = clsd[(size_t)b * NM1 + tid]; taken[tid] = 0; }
    __syncthreads();
    if (tid < NM1) {
        double mv = v[tid];
        int r = 0;
        for (int j = 0; j < NM1; j++) {
            double u = v[j];
            if (u > mv || (u == mv && j < tid)) r++;
        }
        order[r] = tid;
    }
    __syncthreads();
    if (tid < LEFT) {
        int t = order[tid];
        idx[(size_t)b * LEFT + tid] = t;
        taken[t] = 1;
    }
    __syncthreads();
    if (tid == 0) {
        int c = 0;
        for (int j = 0; j < NM1; j++) if (!taken[j]) cmp[(size_t)b * NCMP + (c++)] = j;
    }
}

// ---------------- gather + L2 normalize rows (fp64 norm) ----------------
__global__ void gathnorm_kernel(const float* __restrict__ x1, const int* __restrict__ idx,
                                const int* __restrict__ cmp, float* __restrict__ xon,
                                float* __restrict__ ntn) {
    __shared__ double sh[32];
    const int r = blockIdx.x, b = blockIdx.y;
    int srcn; float* dst;
    if (r < LEFT) { srcn = idx[(size_t)b * LEFT + r]; dst = xon + ((size_t)b * LEFT + r) * CC; }
    else          { srcn = cmp[(size_t)b * NCMP + (r - LEFT)]; dst = ntn + ((size_t)b * NCMP + (r - LEFT)) * CC; }
    const float* src = x1 + ((size_t)b * NN + 1 + srcn) * CC;
    double s = 0.0;
    for (int c = threadIdx.x; c < CC; c += blockDim.x) { double u = (double)src[c]; s += u * u; }
    double nrm = sqrt(blockReduceSumD(s, sh));
    double inv = 1.0 / nrm;
    for (int c = threadIdx.x; c < CC; c += blockDim.x) dst[c] = (float)((double)src[c] * inv);
}

// ---------------- distance argmax (fp64): one block per (m, b) ----------------
__global__ void dist_kernel(const float* __restrict__ xon, const float* __restrict__ ntn,
                            int* __restrict__ nod) {
    const int m = blockIdx.x, b = blockIdx.y, tid = threadIdx.x; // 256 threads
    __shared__ float nt[CC];
    __shared__ double bv[256];
    __shared__ int bi[256];
    for (int c = tid; c < CC; c += blockDim.x) nt[c] = ntn[((size_t)b * NCMP + m) * CC + c];
    __syncthreads();
    double best = -1e300; int besti = 0x7fffffff;
    for (int l = tid; l < LEFT; l += blockDim.x) {
        const float* xr = xon + ((size_t)b * LEFT + l) * CC;
        double s = 0.0;
        for (int c = 0; c < CC; c++) s += (double)nt[c] * (double)xr[c];
        if (s > best || (s == best && l < besti)) { best = s; besti = l; }
    }
    bv[tid] = best; bi[tid] = besti;
    __syncthreads();
    for (int s = 128; s > 0; s >>= 1) {
        if (tid < s) {
            double ov = bv[tid + s]; int oi = bi[tid + s];
            if (ov > bv[tid] || (ov == bv[tid] && oi < bi[tid])) { bv[tid] = ov; bi[tid] = oi; }
        }
        __syncthreads();
    }
    if (tid == 0) nod[(size_t)b * NCMP + m] = bi[0];
}

// ---------------- fuse: weighted gather + deterministic scatter-merge ----------------
__global__ void fuse_kernel(const float* __restrict__ x1, const float* __restrict__ cls,
                            const int* __restrict__ idx, const int* __restrict__ cmp,
                            const int* __restrict__ nod, float* __restrict__ x2) {
    const int l = blockIdx.x, b = blockIdx.y, tid = threadIdx.x;
    __shared__ int mlist[NCMP];
    __shared__ int mcount;
    if (tid == 0) {
        int c = 0;
        for (int m = 0; m < NCMP; m++)
            if (nod[(size_t)b * NCMP + m] == l) mlist[c++] = m;
        mcount = c;
    }
    __syncthreads();
    const int src = idx[(size_t)b * LEFT + l];
    const float a = cls[(size_t)b * NM1 + src];
    float t = a;
    for (int i = 0; i < mcount; i++)
        t += cls[(size_t)b * NM1 + cmp[(size_t)b * NCMP + mlist[i]]];
    const float invt = 1.f / t;
    const float* srow = x1 + ((size_t)b * NN + 1 + src) * CC;
    float* drow = x2 + ((size_t)b * N2 + 1 + l) * CC;
    for (int c = tid; c < CC; c += blockDim.x) {
        float acc = srow[c] * a;
        for (int i = 0; i < mcount; i++) {
            int cm = cmp[(size_t)b * NCMP + mlist[i]];
            acc += x1[((size_t)b * NN + 1 + cm) * CC + c] * cls[(size_t)b * NM1 + cm];
        }
        drow[c] = acc * invt;
    }
}

__global__ void cpycls_kernel(const float* __restrict__ x1, float* __restrict__ x2) {
    const int b = blockIdx.x;
    for (int c = threadIdx.x; c < CC; c += blockDim.x)
        x2[(size_t)b * N2 * CC + c] = x1[(size_t)b * NN * CC + c];
}

// ---------------- launch ----------------
extern "C" void kernel_launch(void* const* d_in, const int* in_sizes, int n_in,
                              void* d_out, int out_size) {
    const float* x       = (const float*)d_in[0];
    const float* norm1_w = (const float*)d_in[1];
    const float* norm1_b = (const float*)d_in[2];
    const float* qkv_w   = (const float*)d_in[3];
    const float* proj_w  = (const float*)d_in[4];
    const float* proj_b  = (const float*)d_in[5];
    const float* norm2_w = (const float*)d_in[6];
    const float* norm2_b = (const float*)d_in[7];
    const float* fc1_w   = (const float*)d_in[8];
    const float* fc1_b   = (const float*)d_in[9];
    const float* fc2_w   = (const float*)d_in[10];
    const float* fc2_b   = (const float*)d_in[11];
    float* out = (float*)d_out;

    float *p_xn, *p_qkv, *p_ao, *p_x1, *p_cls, *p_xon, *p_ntn, *p_x2, *p_xn2, *p_mid;
    double *p_at0d, *p_mu, *p_rs, *p_clsd;
    int *p_idx, *p_cmp, *p_nod;
    cudaGetSymbolAddress((void**)&p_xn,   g_xn);
    cudaGetSymbolAddress((void**)&p_qkv,  g_qkv);
    cudaGetSymbolAddress((void**)&p_ao,   g_ao);
    cudaGetSymbolAddress((void**)&p_x1,   g_x1);
    cudaGetSymbolAddress((void**)&p_mu,   g_mu);
    cudaGetSymbolAddress((void**)&p_rs,   g_rs);
    cudaGetSymbolAddress((void**)&p_at0d, g_at0d);
    cudaGetSymbolAddress((void**)&p_cls,  g_cls);
    cudaGetSymbolAddress((void**)&p_clsd, g_clsd);
    cudaGetSymbolAddress((void**)&p_idx,  g_idx);
    cudaGetSymbolAddress((void**)&p_cmp,  g_cmp);
    cudaGetSymbolAddress((void**)&p_xon,  g_xon);
    cudaGetSymbolAddress((void**)&p_ntn,  g_ntn);
    cudaGetSymbolAddress((void**)&p_nod,  g_nod);
    cudaGetSymbolAddress((void**)&p_x2,   g_x2);
    cudaGetSymbolAddress((void**)&p_xn2,  g_xn2);
    cudaGetSymbolAddress((void**)&p_mid,  g_mid);

    // 1) layernorm1 (fp32 path) + fp64 LN stats (truth path)
    ln_kernel<<<NT, 256>>>(x, norm1_w, norm1_b, p_xn);
    ln64stats_kernel<<<NT, 256>>>(x, p_mu, p_rs);
    // 2) qkv gemm (fp32 path)
    sgemm<<<dim3(H3 / 64, (NT + 63) / 64), 256>>>(p_xn, qkv_w, nullptr, nullptr, p_qkv, NT, H3, CC, 0);
    // 3) attention output (fp32)
    attn_kernel<<<dim3(NN, NHEAD, BB), 128>>>(p_qkv, p_ao);
    // 3b) TRUTH cls probs (fp64, straight from raw inputs)
    cls_truth_kernel<<<dim3(NHEAD, BB), 256>>>(x, qkv_w, norm1_w, norm1_b, p_mu, p_rs, p_at0d);
    // 4) cls attention mean over heads
    clsmean_kernel<<<(BB * NM1 + 255) / 256, 256>>>(p_at0d, p_cls, p_clsd);
    // 5) proj gemm + bias + residual(x)
    sgemm<<<dim3(CC / 64, (NT + 63) / 64), 256>>>(p_ao, proj_w, proj_b, x, p_x1, NT, CC, CC, 1);
    // 6) top-k + complement (exact stable sort on fp64 truth)
    topk_kernel<<<BB, 256>>>(p_clsd, p_idx, p_cmp);
    // 7) gather + normalize
    gathnorm_kernel<<<dim3(LEFT + NCMP, BB), 256>>>(p_x1, p_idx, p_cmp, p_xon, p_ntn);
    // 8) distance argmax (fp64)
    dist_kernel<<<dim3(NCMP, BB), 256>>>(p_xon, p_ntn, p_nod);
    // 9) fuse tokens + cls copy
    fuse_kernel<<<dim3(LEFT, BB), 256>>>(p_x1, p_cls, p_idx, p_cmp, p_nod, p_x2);
    cpycls_kernel<<<BB, 256>>>(p_x1, p_x2);
    // 10) layernorm2
    ln_kernel<<<NT2, 256>>>(p_x2, norm2_w, norm2_b, p_xn2);
    // 11) fc1 + bias + gelu
    sgemm<<<dim3(HID / 64, (NT2 + 63) / 64), 256>>>(p_xn2, fc1_w, fc1_b, nullptr, p_mid, NT2, HID, CC, 2);
    // 12) fc2 + bias + residual(x2) -> out
    sgemm<<<dim3(CC / 64, (NT2 + 63) / 64), 256>>>(p_mid, fc2_w, fc2_b, p_x2, out, NT2, CC, HID, 1);
}

// round 6
// speedup vs baseline: 2.2959x; 2.2959x over previous
#include <cuda_runtime.h>
#include <math.h>
#include <float.h>

// ---------------- problem constants ----------------
#define BB    128
#define NN    197
#define CC    768
#define NHEAD 12
#define HD    64
#define H3    2304          // 3*C
#define HID   3072          // 4*C
#define NT    (BB*NN)       // 25216 tokens (multiple of 128: 128*197)
#define NM1   (NN-1)        // 196
#define LEFT  138           // ceil(0.7*196)
#define NCMP  58            // 196-138
#define N2    (LEFT+1)      // 139
#define NT2   (BB*N2)       // 17792 tokens (multiple of 128: 128*139)

#define KPAD  65
#define SPAD  200

// ---------------- scratch (device globals; no allocations allowed) ----------------
__device__ float  g_xn  [(size_t)NT*CC];       // layernorm1 out (fp32 path)
__device__ float  g_qkv [(size_t)NT*H3];       // qkv
__device__ float  g_ao  [(size_t)NT*CC];       // attention out
__device__ float  g_x1  [(size_t)NT*CC];       // x + proj(out)
__device__ double g_mu  [(size_t)NT];          // fp64 LN1 mean per token
__device__ double g_rs  [(size_t)NT];          // fp64 LN1 rstd per token
__device__ double g_at0d[(size_t)BB*NHEAD*NM1];// fp64 cls row probs (truth)
__device__ float  g_cls [(size_t)BB*NM1];      // mean over heads (fp32, for weights)
__device__ double g_clsd[(size_t)BB*NM1];      // mean over heads (fp64, for selection)
__device__ int    g_idx [(size_t)BB*LEFT];
__device__ int    g_cmp [(size_t)BB*NCMP];
__device__ float  g_xon [(size_t)BB*LEFT*CC];  // normalized topk rows
__device__ float  g_ntn [(size_t)BB*NCMP*CC];  // normalized non-topk rows
__device__ int    g_nod [(size_t)BB*NCMP];     // argmax targets
__device__ float  g_x2  [(size_t)NT2*CC];      // fused tokens
__device__ float  g_xn2 [(size_t)NT2*CC];      // layernorm2 out
__device__ float  g_mid [(size_t)NT2*HID];     // gelu(fc1)

// ---------------- helpers ----------------
__device__ __forceinline__ float blockReduceSum(float v, float* sh) {
    int tid = threadIdx.x;
    #pragma unroll
    for (int o = 16; o > 0; o >>= 1) v += __shfl_down_sync(0xffffffffu, v, o);
    __syncthreads();
    if ((tid & 31) == 0) sh[tid >> 5] = v;
    __syncthreads();
    int nw = blockDim.x >> 5;
    float r = (tid < nw) ? sh[tid] : 0.f;
    if (tid < 32) {
        #pragma unroll
        for (int o = 16; o > 0; o >>= 1) r += __shfl_down_sync(0xffffffffu, r, o);
        if (tid == 0) sh[0] = r;
    }
    __syncthreads();
    return sh[0];
}

__device__ __forceinline__ double blockReduceSumD(double v, double* sh) {
    int tid = threadIdx.x;
    #pragma unroll
    for (int o = 16; o > 0; o >>= 1) v += __shfl_down_sync(0xffffffffu, v, o);
    __syncthreads();
    if ((tid & 31) == 0) sh[tid >> 5] = v;
    __syncthreads();
    int nw = blockDim.x >> 5;
    double r = (tid < nw) ? sh[tid] : 0.0;
    if (tid < 32) {
        #pragma unroll
        for (int o = 16; o > 0; o >>= 1) r += __shfl_down_sync(0xffffffffu, r, o);
        if (tid == 0) sh[0] = r;
    }
    __syncthreads();
    return sh[0];
}

// ---------------- layernorm (fp32 path) ----------------
__global__ void ln_kernel(const float* __restrict__ x, const float* __restrict__ w,
                          const float* __restrict__ b, float* __restrict__ y) {
    __shared__ float sh[32];
    const size_t t = blockIdx.x;
    const float* row = x + t * CC;
    float* out = y + t * CC;
    float s = 0.f;
    for (int c = threadIdx.x; c < CC; c += blockDim.x) s += row[c];
    float mean = blockReduceSum(s, sh) * (1.f / CC);
    float v = 0.f;
    for (int c = threadIdx.x; c < CC; c += blockDim.x) { float d = row[c] - mean; v += d * d; }
    float var = blockReduceSum(v, sh) * (1.f / CC);
    float rstd = rsqrtf(var + 1e-5f);
    for (int c = threadIdx.x; c < CC; c += blockDim.x)
        out[c] = (row[c] - mean) * rstd * w[c] + b[c];
}

// ---------------- fp64 LN stats per token (truth path) ----------------
__global__ void ln64stats_kernel(const float* __restrict__ x, double* __restrict__ mu,
                                 double* __restrict__ rs) {
    __shared__ double sh[32];
    const size_t t = blockIdx.x;
    const float* row = x + t * CC;
    double s = 0.0;
    for (int c = threadIdx.x; c < CC; c += blockDim.x) s += (double)row[c];
    double mean = blockReduceSumD(s, sh) * (1.0 / CC);
    double v = 0.0;
    for (int c = threadIdx.x; c < CC; c += blockDim.x) { double d = (double)row[c] - mean; v += d * d; }
    double var = blockReduceSumD(v, sh) * (1.0 / CC);
    if (threadIdx.x == 0) { mu[t] = mean; rs[t] = rsqrt(var + 1e-5); }
}

// ---------------- truth cls scores: grid (h, b), 256 threads ----------------
__global__ void cls_truth_kernel(const float* __restrict__ x, const float* __restrict__ qw,
                                 const float* __restrict__ n1w, const float* __restrict__ n1b,
                                 const double* __restrict__ mu, const double* __restrict__ rs,
                                 double* __restrict__ at0d) {
    const int h = blockIdx.x, b = blockIdx.y, tid = threadIdx.x; // 256 threads
    __shared__ double xn0[CC];
    __shared__ double q0[HD];
    __shared__ double u[CC];
    __shared__ double sc[NN];
    __shared__ double sh[32];
    const double mu0 = mu[(size_t)b * NN], rs0 = rs[(size_t)b * NN];
    const float* x0 = x + ((size_t)b * NN) * CC;
    for (int c = tid; c < CC; c += blockDim.x)
        xn0[c] = ((double)x0[c] - mu0) * rs0 * (double)n1w[c] + (double)n1b[c];
    __syncthreads();
    if (tid < HD) {
        double a0 = 0.0, a1 = 0.0;
        const float* col = qw + h * HD + tid;
        for (int c = 0; c < CC; c += 2) {
            a0 += xn0[c]     * (double)col[(size_t)c * H3];
            a1 += xn0[c + 1] * (double)col[(size_t)(c + 1) * H3];
        }
        q0[tid] = a0 + a1;
    }
    __syncthreads();
    for (int c = tid; c < CC; c += blockDim.x) {
        const float* rowp = qw + (size_t)c * H3 + CC + h * HD;
        double a0 = 0.0, a1 = 0.0;
        #pragma unroll
        for (int d = 0; d < HD; d += 2) { a0 += (double)rowp[d] * q0[d]; a1 += (double)rowp[d + 1] * q0[d + 1]; }
        u[c] = a0 + a1;
    }
    __syncthreads();
    for (int j = tid; j < NN; j += blockDim.x) {
        const float* xj = x + ((size_t)(b * NN + j)) * CC;
        const double mj = mu[(size_t)b * NN + j], rj = rs[(size_t)b * NN + j];
        double a0 = 0.0, a1 = 0.0;
        for (int c = 0; c < CC; c += 2) {
            a0 += u[c]     * (((double)xj[c]     - mj) * rj * (double)n1w[c]     + (double)n1b[c]);
            a1 += u[c + 1] * (((double)xj[c + 1] - mj) * rj * (double)n1w[c + 1] + (double)n1b[c + 1]);
        }
        sc[j] = (a0 + a1) * 0.125;
    }
    __syncthreads();
    double m = -1e300;
    for (int j = tid; j < NN; j += blockDim.x) m = fmax(m, sc[j]);
    #pragma unroll
    for (int o = 16; o > 0; o >>= 1) m = fmax(m, __shfl_down_sync(0xffffffffu, m, o));
    __syncthreads();
    if ((tid & 31) == 0) sh[tid >> 5] = m;
    __syncthreads();
    if (tid < 32) {
        double r = (tid < (int)(blockDim.x >> 5)) ? sh[tid] : -1e300;
        #pragma unroll
        for (int o = 16; o > 0; o >>= 1) r = fmax(r, __shfl_down_sync(0xffffffffu, r, o));
        if (tid == 0) sh[0] = r;
    }
    __syncthreads();
    m = sh[0];
    __syncthreads();
    double ssum = 0.0;
    for (int j = tid; j < NN; j += blockDim.x) { double e = exp(sc[j] - m); sc[j] = e; ssum += e; }
    double tot = blockReduceSumD(ssum, sh);
    double inv = 1.0 / tot;
    __syncthreads();
    for (int j = tid; j < NM1; j += blockDim.x)
        at0d[((size_t)b * NHEAD + h) * NM1 + j] = sc[j + 1] * inv;
}

// ---------------- cls attention mean over heads ----------------
__global__ void clsmean_kernel(const double* __restrict__ at0d, float* __restrict__ cls,
                               double* __restrict__ clsd) {
    int i = blockIdx.x * blockDim.x + threadIdx.x;
    if (i >= BB * NM1) return;
    int b = i / NM1, j = i % NM1;
    double s = 0.0;
    #pragma unroll
    for (int h = 0; h < NHEAD; h++) s += at0d[((size_t)b * NHEAD + h) * NM1 + j];
    double mval = s * (1.0 / NHEAD);
    clsd[i] = mval;
    cls[i] = (float)mval;
}

// ---------------- SGEMM 128x128 tile, 8x8 micro-tile ----------------
// Requires: M % 128 == 0, Nn % 128 == 0, K % 8 == 0 (true for all our shapes)
// epi: 0=none, 1=bias+residual, 2=bias+gelu(exact)
__global__ __launch_bounds__(256) void sgemm128(const float* __restrict__ A,
                      const float* __restrict__ Bw,
                      const float* __restrict__ bias, const float* __restrict__ Rm,
                      float* __restrict__ Cm, int M, int Nn, int K, int epi) {
    __shared__ float As[8][128];
    __shared__ float Bs[8][128];
    const int tid = threadIdx.x;
    const int tx = tid & 15, ty = tid >> 4;
    const int row0 = blockIdx.y * 128, col0 = blockIdx.x * 128;
    const int am = tid >> 1;            // 0..127
    const int ak = (tid & 1) * 4;       // 0 or 4
    const int bk = tid >> 5;            // 0..7
    const int bn = (tid & 31) * 4;      // 0..124
    float acc[8][8] = {};
    const float* Aptr = A + (size_t)(row0 + am) * K + ak;
    const float* Bptr = Bw + (size_t)bk * Nn + col0 + bn;
    for (int k0 = 0; k0 < K; k0 += 8) {
        float4 av = *(const float4*)(Aptr + k0);
        float4 bv = *(const float4*)(Bptr + (size_t)k0 * Nn);
        As[ak + 0][am] = av.x; As[ak + 1][am] = av.y;
        As[ak + 2][am] = av.z; As[ak + 3][am] = av.w;
        *(float4*)&Bs[bk][bn] = bv;
        __syncthreads();
        #pragma unroll
        for (int kk = 0; kk < 8; kk++) {
            float4 a0 = *(const float4*)&As[kk][ty * 8];
            float4 a1 = *(const float4*)&As[kk][ty * 8 + 4];
            float4 b0 = *(const float4*)&Bs[kk][tx * 8];
            float4 b1 = *(const float4*)&Bs[kk][tx * 8 + 4];
            float ar[8] = {a0.x, a0.y, a0.z, a0.w, a1.x, a1.y, a1.z, a1.w};
            float br[8] = {b0.x, b0.y, b0.z, b0.w, b1.x, b1.y, b1.z, b1.w};
            #pragma unroll
            for (int i = 0; i < 8; i++)
                #pragma unroll
                for (int j = 0; j < 8; j++) acc[i][j] += ar[i] * br[j];
        }
        __syncthreads();
    }
    #pragma unroll
    for (int i = 0; i < 8; i++) {
        int r = row0 + ty * 8 + i;
        float* crow = Cm + (size_t)r * Nn + col0 + tx * 8;
        const float* rrow = (epi == 1) ? (Rm + (size_t)r * Nn + col0 + tx * 8) : nullptr;
        #pragma unroll
        for (int j = 0; j < 8; j++) {
            float v = acc[i][j];
            if (epi != 0) v += bias[col0 + tx * 8 + j];
            if (epi == 1) v += rrow[j];
            else if (epi == 2) v = 0.5f * v * (1.f + erff(v * 0.70710678118654752440f));
            crow[j] = v;
        }
    }
}

// ---------------- attention v2: one block per (h, b), K/V staged in smem ----------------
__global__ __launch_bounds__(256) void attn2_kernel(const float* __restrict__ qkv,
                                                    float* __restrict__ out) {
    extern __shared__ float sm[];
    float* Ks = sm;                       // NN*KPAD
    float* Vs = Ks + NN * KPAD;           // NN*KPAD
    float* Qs = Vs + NN * KPAD;           // 32*KPAD
    float* Ss = Qs + 32 * KPAD;           // 32*SPAD
    const int h = blockIdx.x, b = blockIdx.y, tid = threadIdx.x; // 256 threads
    const float* qbase = qkv + (size_t)b * NN * H3 + h * HD;
    const float* kbase = qkv + (size_t)b * NN * H3 + (NHEAD + h) * HD;
    const float* vbase = qkv + (size_t)b * NN * H3 + (2 * NHEAD + h) * HD;
    // stage K and V (coalesced 64-float row segments)
    for (int idx = tid; idx < NN * HD; idx += 256) {
        int k = idx >> 6, d = idx & 63;
        Ks[k * KPAD + d] = kbase[(size_t)k * H3 + d];
        Vs[k * KPAD + d] = vbase[(size_t)k * H3 + d];
    }
    __syncthreads();
    const int w = tid >> 5, lane = tid & 31;
    for (int qt = 0; qt < NN; qt += 32) {
        const int nq = (NN - qt < 32) ? (NN - qt) : 32;
        // stage Q tile (zero-pad rows beyond nq)
        for (int idx = tid; idx < 32 * HD; idx += 256) {
            int q = idx >> 6, d = idx & 63;
            Qs[q * KPAD + d] = (q < nq) ? qbase[(size_t)(qt + q) * H3 + d] : 0.f;
        }
        __syncthreads();
        // QK: thread owns key k, 32 q accumulators, K-row cached in register chunks
        if (tid < NN) {
            const int k = tid;
            float accq[32];
            #pragma unroll
            for (int q = 0; q < 32; q++) accq[q] = 0.f;
            #pragma unroll
            for (int dc = 0; dc < HD; dc += 16) {
                float kreg[16];
                #pragma unroll
                for (int i = 0; i < 16; i++) kreg[i] = Ks[k * KPAD + dc + i];
                #pragma unroll
                for (int q = 0; q < 32; q++) {
                    float a = accq[q];
                    #pragma unroll
                    for (int i = 0; i < 16; i++) a += kreg[i] * Qs[q * KPAD + dc + i];
                    accq[q] = a;
                }
            }
            #pragma unroll
            for (int q = 0; q < 32; q++)
                if (q < nq) Ss[q * SPAD + k] = accq[q] * 0.125f;
        }
        __syncthreads();
        // softmax: warp per row
        for (int q = w; q < nq; q += 8) {
            float m = -FLT_MAX;
            for (int k = lane; k < NN; k += 32) m = fmaxf(m, Ss[q * SPAD + k]);
            #pragma unroll
            for (int o = 16; o > 0; o >>= 1) m = fmaxf(m, __shfl_xor_sync(0xffffffffu, m, o));
            float s = 0.f;
            for (int k = lane; k < NN; k += 32) {
                float e = expf(Ss[q * SPAD + k] - m);
                Ss[q * SPAD + k] = e; s += e;
            }
            #pragma unroll
            for (int o = 16; o > 0; o >>= 1) s += __shfl_xor_sync(0xffffffffu, s, o);
            float inv = 1.f / s;
            for (int k = lane; k < NN; k += 32) Ss[q * SPAD + k] *= inv;
        }
        __syncthreads();
        // AV: thread (g, d) accumulates 8 q-rows
        {
            const int d = tid & 63, g = tid >> 6; // g: 0..3
            float acc[8];
            #pragma unroll
            for (int j = 0; j < 8; j++) acc[j] = 0.f;
            for (int k = 0; k < NN; k++) {
                float vv = Vs[k * KPAD + d];
                #pragma unroll
                for (int j = 0; j < 8; j++) acc[j] += Ss[(g * 8 + j) * SPAD + k] * vv;
            }
            #pragma unroll
            for (int j = 0; j < 8; j++) {
                int q = qt + g * 8 + j;
                if (g * 8 + j < nq)
                    out[((size_t)(b * NN + q)) * CC + h * HD + d] = acc[j];
            }
        }
        __syncthreads();
    }
}

// ---------------- exact stable descending full sort via rank counting ----------------
__global__ void topk_kernel(const double* __restrict__ clsd, int* __restrict__ idx,
                            int* __restrict__ cmp) {
    const int b = blockIdx.x, tid = threadIdx.x;   // 256 threads
    __shared__ double v[NM1];
    __shared__ int order[NM1];
    __shared__ unsigned char taken[NM1];
    if (tid < NM1) { v[tid] = clsd[(size_t)b * NM1 + tid]; taken[tid] = 0; }
    __syncthreads();
    if (tid < NM1) {
        double mv = v[tid];
        int r = 0;
        for (int j = 0; j < NM1; j++) {
            double u = v[j];
            if (u > mv || (u == mv && j < tid)) r++;
        }
        order[r] = tid;
    }
    __syncthreads();
    if (tid < LEFT) {
        int t = order[tid];
        idx[(size_t)b * LEFT + tid] = t;
        taken[t] = 1;
    }
    __syncthreads();
    if (tid == 0) {
        int c = 0;
        for (int j = 0; j < NM1; j++) if (!taken[j]) cmp[(size_t)b * NCMP + (c++)] = j;
    }
}

// ---------------- gather + L2 normalize rows (fp64 norm) ----------------
__global__ void gathnorm_kernel(const float* __restrict__ x1, const int* __restrict__ idx,
                                const int* __restrict__ cmp, float* __restrict__ xon,
                                float* __restrict__ ntn) {
    __shared__ double sh[32];
    const int r = blockIdx.x, b = blockIdx.y;
    int srcn; float* dst;
    if (r < LEFT) { srcn = idx[(size_t)b * LEFT + r]; dst = xon + ((size_t)b * LEFT + r) * CC; }
    else          { srcn = cmp[(size_t)b * NCMP + (r - LEFT)]; dst = ntn + ((size_t)b * NCMP + (r - LEFT)) * CC; }
    const float* src = x1 + ((size_t)b * NN + 1 + srcn) * CC;
    double s = 0.0;
    for (int c = threadIdx.x; c < CC; c += blockDim.x) { double u = (double)src[c]; s += u * u; }
    double nrm = sqrt(blockReduceSumD(s, sh));
    double inv = 1.0 / nrm;
    for (int c = threadIdx.x; c < CC; c += blockDim.x) dst[c] = (float)((double)src[c] * inv);
}

// ---------------- distance argmax (fp64): one block per (m, b) ----------------
__global__ void dist_kernel(const float* __restrict__ xon, const float* __restrict__ ntn,
                            int* __restrict__ nod) {
    const int m = blockIdx.x, b = blockIdx.y, tid = threadIdx.x; // 256 threads
    __shared__ float nt[CC];
    __shared__ double bv[256];
    __shared__ int bi[256];
    for (int c = tid; c < CC; c += blockDim.x) nt[c] = ntn[((size_t)b * NCMP + m) * CC + c];
    __syncthreads();
    double best = -1e300; int besti = 0x7fffffff;
    for (int l = tid; l < LEFT; l += blockDim.x) {
        const float* xr = xon + ((size_t)b * LEFT + l) * CC;
        double s = 0.0;
        for (int c = 0; c < CC; c++) s += (double)nt[c] * (double)xr[c];
        if (s > best || (s == best && l < besti)) { best = s; besti = l; }
    }
    bv[tid] = best; bi[tid] = besti;
    __syncthreads();
    for (int s = 128; s > 0; s >>= 1) {
        if (tid < s) {
            double ov = bv[tid + s]; int oi = bi[tid + s];
            if (ov > bv[tid] || (ov == bv[tid] && oi < bi[tid])) { bv[tid] = ov; bi[tid] = oi; }
        }
        __syncthreads();
    }
    if (tid == 0) nod[(size_t)b * NCMP + m] = bi[0];
}

// ---------------- fuse: weighted gather + deterministic scatter-merge ----------------
__global__ void fuse_kernel(const float* __restrict__ x1, const float* __restrict__ cls,
                            const int* __restrict__ idx, const int* __restrict__ cmp,
                            const int* __restrict__ nod, float* __restrict__ x2) {
    const int l = blockIdx.x, b = blockIdx.y, tid = threadIdx.x;
    __shared__ int mlist[NCMP];
    __shared__ int mcount;
    if (tid == 0) {
        int c = 0;
        for (int m = 0; m < NCMP; m++)
            if (nod[(size_t)b * NCMP + m] == l) mlist[c++] = m;
        mcount = c;
    }
    __syncthreads();
    const int src = idx[(size_t)b * LEFT + l];
    const float a = cls[(size_t)b * NM1 + src];
    float t = a;
    for (int i = 0; i < mcount; i++)
        t += cls[(size_t)b * NM1 + cmp[(size_t)b * NCMP + mlist[i]]];
    const float invt = 1.f / t;
    const float* srow = x1 + ((size_t)b * NN + 1 + src) * CC;
    float* drow = x2 + ((size_t)b * N2 + 1 + l) * CC;
    for (int c = tid; c < CC; c += blockDim.x) {
        float acc = srow[c] * a;
        for (int i = 0; i < mcount; i++) {
            int cm = cmp[(size_t)b * NCMP + mlist[i]];
            acc += x1[((size_t)b * NN + 1 + cm) * CC + c] * cls[(size_t)b * NM1 + cm];
        }
        drow[c] = acc * invt;
    }
}

__global__ void cpycls_kernel(const float* __restrict__ x1, float* __restrict__ x2) {
    const int b = blockIdx.x;
    for (int c = threadIdx.x; c < CC; c += blockDim.x)
        x2[(size_t)b * N2 * CC + c] = x1[(size_t)b * NN * CC + c];
}

// ---------------- launch ----------------
extern "C" void kernel_launch(void* const* d_in, const int* in_sizes, int n_in,
                              void* d_out, int out_size) {
    const float* x       = (const float*)d_in[0];
    const float* norm1_w = (const float*)d_in[1];
    const float* norm1_b = (const float*)d_in[2];
    const float* qkv_w   = (const float*)d_in[3];
    const float* proj_w  = (const float*)d_in[4];
    const float* proj_b  = (const float*)d_in[5];
    const float* norm2_w = (const float*)d_in[6];
    const float* norm2_b = (const float*)d_in[7];
    const float* fc1_w   = (const float*)d_in[8];
    const float* fc1_b   = (const float*)d_in[9];
    const float* fc2_w   = (const float*)d_in[10];
    const float* fc2_b   = (const float*)d_in[11];
    float* out = (float*)d_out;

    float *p_xn, *p_qkv, *p_ao, *p_x1, *p_cls, *p_xon, *p_ntn, *p_x2, *p_xn2, *p_mid;
    double *p_at0d, *p_mu, *p_rs, *p_clsd;
    int *p_idx, *p_cmp, *p_nod;
    cudaGetSymbolAddress((void**)&p_xn,   g_xn);
    cudaGetSymbolAddress((void**)&p_qkv,  g_qkv);
    cudaGetSymbolAddress((void**)&p_ao,   g_ao);
    cudaGetSymbolAddress((void**)&p_x1,   g_x1);
    cudaGetSymbolAddress((void**)&p_mu,   g_mu);
    cudaGetSymbolAddress((void**)&p_rs,   g_rs);
    cudaGetSymbolAddress((void**)&p_at0d, g_at0d);
    cudaGetSymbolAddress((void**)&p_cls,  g_cls);
    cudaGetSymbolAddress((void**)&p_clsd, g_clsd);
    cudaGetSymbolAddress((void**)&p_idx,  g_idx);
    cudaGetSymbolAddress((void**)&p_cmp,  g_cmp);
    cudaGetSymbolAddress((void**)&p_xon,  g_xon);
    cudaGetSymbolAddress((void**)&p_ntn,  g_ntn);
    cudaGetSymbolAddress((void**)&p_nod,  g_nod);
    cudaGetSymbolAddress((void**)&p_x2,   g_x2);
    cudaGetSymbolAddress((void**)&p_xn2,  g_xn2);
    cudaGetSymbolAddress((void**)&p_mid,  g_mid);

    // attention v2 dynamic smem: (2*NN + 32)*KPAD + 32*SPAD floats
    const int attn_smem = ((2 * NN + 32) * KPAD + 32 * SPAD) * (int)sizeof(float);
    static int attn_attr_set = 0;
    if (!attn_attr_set) {
        cudaFuncSetAttribute(attn2_kernel, cudaFuncAttributeMaxDynamicSharedMemorySize, attn_smem);
        attn_attr_set = 1;
    }

    // 1) layernorm1 (fp32 path) + fp64 LN stats (truth path)
    ln_kernel<<<NT, 256>>>(x, norm1_w, norm1_b, p_xn);
    ln64stats_kernel<<<NT, 256>>>(x, p_mu, p_rs);
    // 2) qkv gemm (fp32 path)
    sgemm128<<<dim3(H3 / 128, NT / 128), 256>>>(p_xn, qkv_w, nullptr, nullptr, p_qkv, NT, H3, CC, 0);
    // 3) attention output (fp32, smem-staged)
    attn2_kernel<<<dim3(NHEAD, BB), 256, attn_smem>>>(p_qkv, p_ao);
    // 3b) TRUTH cls probs (fp64, straight from raw inputs)
    cls_truth_kernel<<<dim3(NHEAD, BB), 256>>>(x, qkv_w, norm1_w, norm1_b, p_mu, p_rs, p_at0d);
    // 4) cls attention mean over heads
    clsmean_kernel<<<(BB * NM1 + 255) / 256, 256>>>(p_at0d, p_cls, p_clsd);
    // 5) proj gemm + bias + residual(x)
    sgemm128<<<dim3(CC / 128, NT / 128), 256>>>(p_ao, proj_w, proj_b, x, p_x1, NT, CC, CC, 1);
    // 6) top-k + complement (exact stable sort on fp64 truth)
    topk_kernel<<<BB, 256>>>(p_clsd, p_idx, p_cmp);
    // 7) gather + normalize
    gathnorm_kernel<<<dim3(LEFT + NCMP, BB), 256>>>(p_x1, p_idx, p_cmp, p_xon, p_ntn);
    // 8) distance argmax (fp64)
    dist_kernel<<<dim3(NCMP, BB), 256>>>(p_xon, p_ntn, p_nod);
    // 9) fuse tokens + cls copy
    fuse_kernel<<<dim3(LEFT, BB), 256>>>(p_x1, p_cls, p_idx, p_cmp, p_nod, p_x2);
    cpycls_kernel<<<BB, 256>>>(p_x1, p_x2);
    // 10) layernorm2
    ln_kernel<<<NT2, 256>>>(p_x2, norm2_w, norm2_b, p_xn2);
    // 11) fc1 + bias + gelu
    sgemm128<<<dim3(HID / 128, NT2 / 128), 256>>>(p_xn2, fc1_w, fc1_b, nullptr, p_mid, NT2, HID, CC, 2);
    // 12) fc2 + bias + residual(x2) -> out
    sgemm128<<<dim3(CC / 128, NT2 / 128), 256>>>(p_mid, fc2_w, fc2_b, p_x2, out, NT2, CC, HID, 1);
}